// round 1
// baseline (speedup 1.0000x reference)
#include <cuda_runtime.h>
#include <cstdint>

#define SLEN 2048
#define EDIM 512
#define HDIM 256
#define NTAG 32
#define START_TAG 30
#define STOP_TAG 31
#define NEGV (-10000.0f)

// ---------------- scratch (device globals; no runtime alloc) ----------------
__device__ float g_emb[SLEN * EDIM];            // gathered embeddings  [S][E]
__device__ float g_px[2][SLEN * 4 * HDIM];      // input projections    [dir][S][4H]
__device__ float g_h[2][SLEN * HDIM];           // hidden outputs       [dir][S][H]
__device__ float g_feats[SLEN * NTAG];          // tag scores           [S][T]

// ---------------- K0: embedding gather ----------------
__global__ void gather_kernel(const int* __restrict__ sent,
                              const float* __restrict__ embed) {
    int s = blockIdx.x;
    int row = sent[s];
    const float4* src = (const float4*)(embed + (size_t)row * EDIM);
    float4* dst = (float4*)(g_emb + s * EDIM);
    dst[threadIdx.x] = src[threadIdx.x];   // 128 threads * float4 = 512 floats
}

// ---------------- K1: px = emb @ W_ih^T + b  (SGEMM 2048x1024x512, per dir) ----
#define BM 128
#define BN 128
#define BK 16
#define SPAD 132

__global__ __launch_bounds__(256) void px_gemm_kernel(
    const float* __restrict__ w_f, const float* __restrict__ b_f,
    const float* __restrict__ w_b, const float* __restrict__ b_b)
{
    int dir = blockIdx.z;
    const float* W = dir ? w_b : w_f;
    const float* bias = dir ? b_b : b_f;
    float* C = g_px[dir];

    __shared__ float As[BK * SPAD];
    __shared__ float Bs[BK * SPAD];

    int tid = threadIdx.x;
    int m_block = blockIdx.x * BM;
    int n_block = blockIdx.y * BN;

    int lm = tid >> 2;          // 0..63
    int lk4 = (tid & 3) * 4;    // 0,4,8,12

    int ty = tid >> 4;          // 0..15
    int tx = tid & 15;          // 0..15
    int m0 = ty * 8, n0 = tx * 8;

    float acc[8][8];
#pragma unroll
    for (int i = 0; i < 8; i++)
#pragma unroll
        for (int j = 0; j < 8; j++) acc[i][j] = 0.f;

    for (int kt = 0; kt < EDIM; kt += BK) {
#pragma unroll
        for (int h = 0; h < 2; h++) {
            int m = lm + h * 64;
            float4 a = *(const float4*)(g_emb + (m_block + m) * EDIM + kt + lk4);
            As[(lk4 + 0) * SPAD + m] = a.x;
            As[(lk4 + 1) * SPAD + m] = a.y;
            As[(lk4 + 2) * SPAD + m] = a.z;
            As[(lk4 + 3) * SPAD + m] = a.w;
            float4 b = *(const float4*)(W + (size_t)(n_block + m) * EDIM + kt + lk4);
            Bs[(lk4 + 0) * SPAD + m] = b.x;
            Bs[(lk4 + 1) * SPAD + m] = b.y;
            Bs[(lk4 + 2) * SPAD + m] = b.z;
            Bs[(lk4 + 3) * SPAD + m] = b.w;
        }
        __syncthreads();
#pragma unroll
        for (int k = 0; k < BK; k++) {
            float ar[8], br[8];
            *(float4*)(ar + 0) = *(const float4*)(&As[k * SPAD + m0 + 0]);
            *(float4*)(ar + 4) = *(const float4*)(&As[k * SPAD + m0 + 4]);
            *(float4*)(br + 0) = *(const float4*)(&Bs[k * SPAD + n0 + 0]);
            *(float4*)(br + 4) = *(const float4*)(&Bs[k * SPAD + n0 + 4]);
#pragma unroll
            for (int i = 0; i < 8; i++)
#pragma unroll
                for (int j = 0; j < 8; j++) acc[i][j] += ar[i] * br[j];
        }
        __syncthreads();
    }
#pragma unroll
    for (int i = 0; i < 8; i++) {
        int row = m_block + m0 + i;
#pragma unroll
        for (int j4 = 0; j4 < 8; j4 += 4) {
            int n = n_block + n0 + j4;
            float4 v;
            v.x = acc[i][j4 + 0] + bias[n + 0];
            v.y = acc[i][j4 + 1] + bias[n + 1];
            v.z = acc[i][j4 + 2] + bias[n + 2];
            v.w = acc[i][j4 + 3] + bias[n + 3];
            *(float4*)(C + row * (4 * HDIM) + n) = v;
        }
    }
}

// ---------------- K2: recurrent LSTM (8-CTA cluster per direction) ----------
// CTA `crank` owns hidden units [crank*32, crank*32+32). Its 128 rows of
// w_hh (gates i,f,g,o for those units) live in SMEM (128 KB). Per step:
// every thread computes a half-row dot, reduce, 32 threads apply gates,
// broadcast new h to all 8 CTAs' double-buffered h via DSMEM, one cluster sync.
#define WPAD 260
#define LSTM_SMEM ((128 * WPAD + 2 * HDIM + 256) * 4)

__global__ void __cluster_dims__(8, 1, 1) __launch_bounds__(256) lstm_kernel(
    const float* __restrict__ w_hh_f, const float* __restrict__ w_hh_b,
    const float* __restrict__ h0, const float* __restrict__ c0)
{
    extern __shared__ float sm[];
    float* Wsm = sm;                     // [128][WPAD]
    float* hbuf = sm + 128 * WPAD;       // [2][256] double buffer
    float* red = hbuf + 2 * HDIM;        // [256]

    int tid = threadIdx.x;
    int dir = blockIdx.x >> 3;
    int crank = blockIdx.x & 7;
    int base_u = crank * 32;

    const float* Whh = dir ? w_hh_b : w_hh_f;
    const float* px = g_px[dir];
    float* hout = g_h[dir];

    // stage this CTA's 128 weight rows (row-major, padded stride: conflict-free)
    for (int idx = tid; idx < 128 * 256; idx += 256) {
        int lr = idx >> 8;        // local row 0..127 (= gate*32 + j)
        int k = idx & 255;
        int gr = ((lr >> 5) << 8) + base_u + (lr & 31);  // global row in [0,1024)
        Wsm[lr * WPAD + k] = Whh[gr * 256 + k];
    }
    hbuf[tid] = (tid < 256) ? h0[dir * HDIM + (tid & 255)] : 0.f;
    if (tid < 256) hbuf[tid] = h0[dir * HDIM + tid];

    int u = base_u + tid;                 // meaningful for tid<32
    float c_reg = (tid < 32) ? c0[dir * HDIM + u] : 0.f;
    __syncthreads();

    uint32_t hbuf_sa = (uint32_t)__cvta_generic_to_shared(hbuf);

    int half = tid >> 7;                  // k-half (0/1)
    int lr = tid & 127;                   // local row
    const float4* wrow = (const float4*)(Wsm + lr * WPAD + half * 128);

    int cur = 0;
    for (int step = 0; step < SLEN; step++) {
        int s = dir ? (SLEN - 1 - step) : step;
        float pxi = 0.f, pxf = 0.f, pxg = 0.f, pxo = 0.f;
        if (tid < 32) {                   // prefetch px early; hidden by dot loop
            const float* prow = px + s * 1024;
            pxi = __ldg(prow + u);
            pxf = __ldg(prow + 256 + u);
            pxg = __ldg(prow + 512 + u);
            pxo = __ldg(prow + 768 + u);
        }
        const float4* h4 = (const float4*)(hbuf + cur * HDIM) + half * 32;
        float acc = 0.f;
#pragma unroll
        for (int i = 0; i < 32; i++) {
            float4 w = wrow[i];
            float4 h = h4[i];
            acc += w.x * h.x;
            acc += w.y * h.y;
            acc += w.z * h.z;
            acc += w.w * h.w;
        }
        red[tid] = acc;
        __syncthreads();
        if (tid < 32) {
            float di = red[tid] + red[128 + tid];
            float df = red[32 + tid] + red[160 + tid];
            float dg = red[64 + tid] + red[192 + tid];
            float dz = red[96 + tid] + red[224 + tid];
            float ig = 1.f / (1.f + __expf(-(pxi + di)));
            float fg = 1.f / (1.f + __expf(-(pxf + df)));
            float gg = tanhf(pxg + dg);
            float og = 1.f / (1.f + __expf(-(pxo + dz)));
            c_reg = fg * c_reg + ig * gg;
            float hnew = og * tanhf(c_reg);
            hout[s * HDIM + u] = hnew;
            // broadcast into the *other* h buffer of every CTA in the cluster
            uint32_t dst = hbuf_sa + ((((cur ^ 1) * HDIM) + u) << 2);
#pragma unroll
            for (int r = 0; r < 8; r++) {
                uint32_t ra;
                asm volatile("mapa.shared::cluster.u32 %0, %1, %2;"
                             : "=r"(ra) : "r"(dst), "r"(r));
                asm volatile("st.shared::cluster.f32 [%0], %1;"
                             :: "r"(ra), "f"(hnew) : "memory");
            }
        }
        cur ^= 1;
        asm volatile("barrier.cluster.arrive.aligned;" ::: "memory");
        asm volatile("barrier.cluster.wait.aligned;" ::: "memory");
    }
}

// ---------------- K3: feats = [h_fwd|h_bwd] @ w_tag^T + b_tag ----------------
__global__ __launch_bounds__(256) void feats_kernel(const float* __restrict__ w_tag,
                                                    const float* __restrict__ b_tag)
{
    int warp = threadIdx.x >> 5;
    int lane = threadIdx.x & 31;
    int s = blockIdx.x * 8 + warp;
    const float* hf = g_h[0] + s * HDIM;
    const float* hb = g_h[1] + s * HDIM;
    const float* w = w_tag + lane * (2 * HDIM);
    float acc = b_tag[lane];
#pragma unroll 8
    for (int k = 0; k < HDIM; k++) acc += hf[k] * w[k];
#pragma unroll 8
    for (int k = 0; k < HDIM; k++) acc += hb[k] * w[HDIM + k];
    g_feats[s * NTAG + lane] = acc;
}

// ---------------- K4: Viterbi forward + backtrace -----------------------------
__global__ void __launch_bounds__(32) viterbi_kernel(const float* __restrict__ trans,
                                                     float* __restrict__ out,
                                                     int out_size)
{
    extern __shared__ unsigned char bp[];   // [S][32] backpointers (64 KB)
    int n = threadIdx.x;
    float tr[NTAG];
#pragma unroll
    for (int p = 0; p < NTAG; p++) tr[p] = trans[n * NTAG + p];

    float fv = (n == START_TAG) ? 0.f : NEGV;
    float feat = g_feats[n];                // t=0 prefetched
    for (int t = 0; t < SLEN; t++) {
        float feat_next = (t + 1 < SLEN) ? g_feats[(t + 1) * NTAG + n] : 0.f;
        float best = -3.4e38f;
        int bi = 0;
#pragma unroll
        for (int p = 0; p < NTAG; p++) {
            float v = __shfl_sync(0xffffffffu, fv, p) + tr[p];
            if (v > best) { best = v; bi = p; }   // strict > keeps FIRST max (jnp.argmax)
        }
        fv = best + feat;
        bp[t * NTAG + n] = (unsigned char)bi;
        feat = feat_next;
    }
    // terminal scores + warp argmax (first-index tie rule)
    float term = fv + trans[STOP_TAG * NTAG + n];
    float bv = term;
    int bi2 = n;
#pragma unroll
    for (int off = 16; off > 0; off >>= 1) {
        float ov = __shfl_down_sync(0xffffffffu, bv, off);
        int oi = __shfl_down_sync(0xffffffffu, bi2, off);
        if (ov > bv || (ov == bv && oi < bi2)) { bv = ov; bi2 = oi; }
    }
    if (n == 0) {
        if (out_size > 0) out[0] = bv;                      // path score
        int tag = bi2;
        if (out_size > SLEN) out[SLEN] = (float)tag;        // tag_seq[S-1]
        for (int t = SLEN - 2; t >= 0; t--) {
            tag = bp[(t + 1) * NTAG + tag];
            if (1 + t < out_size) out[1 + t] = (float)tag;  // tag_seq[t]
        }
    }
}

// ---------------- launch -----------------------------------------------------
extern "C" void kernel_launch(void* const* d_in, const int* in_sizes, int n_in,
                              void* d_out, int out_size)
{
    const int*   sent   = (const int*)d_in[0];
    const float* embed  = (const float*)d_in[1];
    const float* w_ih_f = (const float*)d_in[2];
    const float* w_hh_f = (const float*)d_in[3];
    const float* b_f    = (const float*)d_in[4];
    const float* w_ih_b = (const float*)d_in[5];
    const float* w_hh_b = (const float*)d_in[6];
    const float* b_b    = (const float*)d_in[7];
    const float* w_tag  = (const float*)d_in[8];
    const float* b_tag  = (const float*)d_in[9];
    const float* trans  = (const float*)d_in[10];
    const float* h0     = (const float*)d_in[11];
    const float* c0     = (const float*)d_in[12];
    float* out = (float*)d_out;

    cudaFuncSetAttribute(lstm_kernel,
                         cudaFuncAttributeMaxDynamicSharedMemorySize, LSTM_SMEM);
    cudaFuncSetAttribute(viterbi_kernel,
                         cudaFuncAttributeMaxDynamicSharedMemorySize, SLEN * NTAG);

    gather_kernel<<<SLEN, EDIM / 4>>>(sent, embed);

    dim3 gg(SLEN / BM, (4 * HDIM) / BN, 2);
    px_gemm_kernel<<<gg, 256>>>(w_ih_f, b_f, w_ih_b, b_b);

    lstm_kernel<<<16, 256, LSTM_SMEM>>>(w_hh_f, w_hh_b, h0, c0);

    feats_kernel<<<SLEN / 8, 256>>>(w_tag, b_tag);

    viterbi_kernel<<<1, 32, SLEN * NTAG>>>(trans, out, out_size);
}

// round 2
// speedup vs baseline: 1.2152x; 1.2152x over previous
#include <cuda_runtime.h>
#include <cstdint>

#define SLEN 2048
#define EDIM 512
#define HDIM 256
#define NTAG 32
#define START_TAG 30
#define STOP_TAG 31
#define NEGV (-10000.0f)

// ---------------- scratch (device globals; no runtime alloc) ----------------
__device__ float g_emb[SLEN * EDIM];            // gathered embeddings  [S][E]
__device__ float g_px[2][SLEN * 4 * HDIM];      // input projections    [dir][S][4H]
__device__ float g_h[2][SLEN * HDIM];           // hidden outputs       [dir][S][H]
__device__ float g_feats[SLEN * NTAG];          // tag scores           [S][T]

// ---------------- K0: embedding gather ----------------
__global__ void gather_kernel(const int* __restrict__ sent,
                              const float* __restrict__ embed) {
    int s = blockIdx.x;
    int row = sent[s];
    const float4* src = (const float4*)(embed + (size_t)row * EDIM);
    float4* dst = (float4*)(g_emb + s * EDIM);
    dst[threadIdx.x] = src[threadIdx.x];
}

// ---------------- K1: px = emb @ W_ih^T + b  (SGEMM 2048x1024x512, per dir) ----
#define BM 128
#define BN 128
#define BK 16
#define SPAD 132

__global__ __launch_bounds__(256) void px_gemm_kernel(
    const float* __restrict__ w_f, const float* __restrict__ b_f,
    const float* __restrict__ w_b, const float* __restrict__ b_b)
{
    int dir = blockIdx.z;
    const float* W = dir ? w_b : w_f;
    const float* bias = dir ? b_b : b_f;
    float* C = g_px[dir];

    __shared__ float As[BK * SPAD];
    __shared__ float Bs[BK * SPAD];

    int tid = threadIdx.x;
    int m_block = blockIdx.x * BM;
    int n_block = blockIdx.y * BN;

    int lm = tid >> 2;
    int lk4 = (tid & 3) * 4;
    int ty = tid >> 4;
    int tx = tid & 15;
    int m0 = ty * 8, n0 = tx * 8;

    float acc[8][8];
#pragma unroll
    for (int i = 0; i < 8; i++)
#pragma unroll
        for (int j = 0; j < 8; j++) acc[i][j] = 0.f;

    for (int kt = 0; kt < EDIM; kt += BK) {
#pragma unroll
        for (int h = 0; h < 2; h++) {
            int m = lm + h * 64;
            float4 a = *(const float4*)(g_emb + (m_block + m) * EDIM + kt + lk4);
            As[(lk4 + 0) * SPAD + m] = a.x;
            As[(lk4 + 1) * SPAD + m] = a.y;
            As[(lk4 + 2) * SPAD + m] = a.z;
            As[(lk4 + 3) * SPAD + m] = a.w;
            float4 b = *(const float4*)(W + (size_t)(n_block + m) * EDIM + kt + lk4);
            Bs[(lk4 + 0) * SPAD + m] = b.x;
            Bs[(lk4 + 1) * SPAD + m] = b.y;
            Bs[(lk4 + 2) * SPAD + m] = b.z;
            Bs[(lk4 + 3) * SPAD + m] = b.w;
        }
        __syncthreads();
#pragma unroll
        for (int k = 0; k < BK; k++) {
            float ar[8], br[8];
            *(float4*)(ar + 0) = *(const float4*)(&As[k * SPAD + m0 + 0]);
            *(float4*)(ar + 4) = *(const float4*)(&As[k * SPAD + m0 + 4]);
            *(float4*)(br + 0) = *(const float4*)(&Bs[k * SPAD + n0 + 0]);
            *(float4*)(br + 4) = *(const float4*)(&Bs[k * SPAD + n0 + 4]);
#pragma unroll
            for (int i = 0; i < 8; i++)
#pragma unroll
                for (int j = 0; j < 8; j++) acc[i][j] += ar[i] * br[j];
        }
        __syncthreads();
    }
#pragma unroll
    for (int i = 0; i < 8; i++) {
        int row = m_block + m0 + i;
#pragma unroll
        for (int j4 = 0; j4 < 8; j4 += 4) {
            int n = n_block + n0 + j4;
            float4 v;
            v.x = acc[i][j4 + 0] + bias[n + 0];
            v.y = acc[i][j4 + 1] + bias[n + 1];
            v.z = acc[i][j4 + 2] + bias[n + 2];
            v.w = acc[i][j4 + 3] + bias[n + 3];
            *(float4*)(C + row * (4 * HDIM) + n) = v;
        }
    }
}

// ---------------- K2: recurrent LSTM, W in REGISTERS, 8-CTA cluster/dir -----
// CTA `crank` owns hidden units [crank*32, +32). Each thread holds 128 floats
// of w_hh in registers (64 x f32x2). Per step: only h (1KB, broadcast LDS)
// moves through SMEM; dot = 64 packed FMAs on 4 independent chains.
__global__ void __cluster_dims__(8, 1, 1) __launch_bounds__(256, 1) lstm_kernel(
    const float* __restrict__ w_hh_f, const float* __restrict__ w_hh_b,
    const float* __restrict__ h0, const float* __restrict__ c0)
{
    __shared__ float hbuf[2 * HDIM];
    __shared__ float red[256];

    int tid = threadIdx.x;
    int dir = blockIdx.x >> 3;
    int crank = blockIdx.x & 7;
    int base_u = crank * 32;

    const float* Whh = dir ? w_hh_b : w_hh_f;
    const float* px = g_px[dir];
    float* hout = g_h[dir];

    int lr = tid & 127;                   // local row 0..127 (= gate*32 + j)
    int half = tid >> 7;                  // k-half
    int gr = ((lr >> 5) << 8) + base_u + (lr & 31);   // global gate row

    // one-time: load this thread's 128 weights into registers (packed pairs)
    uint64_t w2[64];
    const uint64_t* wsrc = (const uint64_t*)(Whh + (size_t)gr * 256 + half * 128);
#pragma unroll
    for (int j = 0; j < 64; j++) w2[j] = wsrc[j];

    hbuf[tid < 256 ? tid : 0] = h0[dir * HDIM + (tid & 255)];
    int u = base_u + tid;                 // meaningful for tid<32
    float c_reg = (tid < 32) ? c0[dir * HDIM + u] : 0.f;
    __syncthreads();

    uint32_t hbuf_sa = (uint32_t)__cvta_generic_to_shared(hbuf);

    int cur = 0;
    for (int step = 0; step < SLEN; step++) {
        int s = dir ? (SLEN - 1 - step) : step;
        float pxi = 0.f, pxf = 0.f, pxg = 0.f, pxo = 0.f;
        if (tid < 32) {                   // L2-latency hidden by dot loop
            const float* prow = px + s * 1024;
            pxi = __ldg(prow + u);
            pxf = __ldg(prow + 256 + u);
            pxg = __ldg(prow + 512 + u);
            pxo = __ldg(prow + 768 + u);
        }
        const uint64_t* h2 = (const uint64_t*)(hbuf + cur * HDIM) + half * 64;
        uint64_t a0 = 0ull, a1 = 0ull, a2 = 0ull, a3 = 0ull;
#pragma unroll
        for (int j = 0; j < 64; j += 4) {
            uint64_t h0v = h2[j + 0], h1v = h2[j + 1], h2v = h2[j + 2], h3v = h2[j + 3];
            asm("fma.rn.f32x2 %0, %1, %2, %0;" : "+l"(a0) : "l"(w2[j + 0]), "l"(h0v));
            asm("fma.rn.f32x2 %0, %1, %2, %0;" : "+l"(a1) : "l"(w2[j + 1]), "l"(h1v));
            asm("fma.rn.f32x2 %0, %1, %2, %0;" : "+l"(a2) : "l"(w2[j + 2]), "l"(h2v));
            asm("fma.rn.f32x2 %0, %1, %2, %0;" : "+l"(a3) : "l"(w2[j + 3]), "l"(h3v));
        }
        float l0, h0f, l1, h1f, l2, h2f, l3, h3f;
        asm("mov.b64 {%0,%1}, %2;" : "=f"(l0), "=f"(h0f) : "l"(a0));
        asm("mov.b64 {%0,%1}, %2;" : "=f"(l1), "=f"(h1f) : "l"(a1));
        asm("mov.b64 {%0,%1}, %2;" : "=f"(l2), "=f"(h2f) : "l"(a2));
        asm("mov.b64 {%0,%1}, %2;" : "=f"(l3), "=f"(h3f) : "l"(a3));
        red[tid] = ((l0 + h0f) + (l1 + h1f)) + ((l2 + h2f) + (l3 + h3f));
        __syncthreads();
        if (tid < 32) {
            float di = red[tid] + red[128 + tid];
            float df = red[32 + tid] + red[160 + tid];
            float dg = red[64 + tid] + red[192 + tid];
            float dz = red[96 + tid] + red[224 + tid];
            float ig = 1.f / (1.f + __expf(-(pxi + di)));
            float fg = 1.f / (1.f + __expf(-(pxf + df)));
            float gg = tanhf(pxg + dg);
            float og = 1.f / (1.f + __expf(-(pxo + dz)));
            c_reg = fg * c_reg + ig * gg;
            float hnew = og * tanhf(c_reg);
            hout[s * HDIM + u] = hnew;
            uint32_t dst = hbuf_sa + ((((cur ^ 1) * HDIM) + u) << 2);
#pragma unroll
            for (int r = 0; r < 8; r++) {
                uint32_t ra;
                asm volatile("mapa.shared::cluster.u32 %0, %1, %2;"
                             : "=r"(ra) : "r"(dst), "r"(r));
                asm volatile("st.shared::cluster.f32 [%0], %1;"
                             :: "r"(ra), "f"(hnew) : "memory");
            }
        }
        cur ^= 1;
        asm volatile("barrier.cluster.arrive.aligned;" ::: "memory");
        asm volatile("barrier.cluster.wait.aligned;" ::: "memory");
    }
}

// ---------------- K3: feats = [h_fwd|h_bwd] @ w_tag^T + b_tag ----------------
// w_tag transposed into padded smem (conflict-free), h staged per warp.
#define FEATS_SMEM ((512 * 33 + 8 * 512) * 4)
__global__ __launch_bounds__(256) void feats_kernel(const float* __restrict__ w_tag,
                                                    const float* __restrict__ b_tag)
{
    extern __shared__ float fs[];
    float* wt = fs;                 // [512][33]
    float* hs = fs + 512 * 33;      // [8 warps][512]

    int tid = threadIdx.x;
    for (int idx = tid; idx < NTAG * 512; idx += 256) {
        int t = idx >> 9;           // tag
        int k = idx & 511;
        wt[k * 33 + t] = w_tag[idx];
    }
    __syncthreads();

    int warp = tid >> 5, lane = tid & 31;
    float bias = b_tag[lane];
    float* hrow = hs + warp * 512;

#pragma unroll
    for (int p = 0; p < 4; p++) {
        int s = blockIdx.x * 32 + p * 8 + warp;
        float4* dsth = (float4*)hrow;
        const float4* hf4 = (const float4*)(g_h[0] + s * HDIM);
        const float4* hb4 = (const float4*)(g_h[1] + s * HDIM);
        dsth[lane] = hf4[lane];
        dsth[32 + lane] = hf4[32 + lane];
        dsth[64 + lane] = hb4[lane];
        dsth[96 + lane] = hb4[32 + lane];
        __syncwarp();
        float a0 = 0.f, a1 = 0.f, a2 = 0.f, a3 = 0.f;
#pragma unroll 8
        for (int k = 0; k < 512; k += 4) {
            float4 h = *(const float4*)(hrow + k);
            a0 += wt[(k + 0) * 33 + lane] * h.x;
            a1 += wt[(k + 1) * 33 + lane] * h.y;
            a2 += wt[(k + 2) * 33 + lane] * h.z;
            a3 += wt[(k + 3) * 33 + lane] * h.w;
        }
        g_feats[s * NTAG + lane] = (a0 + a1) + (a2 + a3) + bias;
        __syncwarp();
    }
}

// ---------------- K4: Viterbi forward + backtrace -----------------------------
__global__ void __launch_bounds__(32) viterbi_kernel(const float* __restrict__ trans,
                                                     float* __restrict__ out,
                                                     int out_size)
{
    extern __shared__ unsigned char bp[];   // [S][32] backpointers (64 KB)
    int n = threadIdx.x;
    float tr[NTAG];
#pragma unroll
    for (int p = 0; p < NTAG; p++) tr[p] = trans[n * NTAG + p];

    float fv = (n == START_TAG) ? 0.f : NEGV;
    float f0 = g_feats[n];
    float f1 = g_feats[NTAG + n];
    for (int t = 0; t < SLEN; t++) {
        float f2 = (t + 2 < SLEN) ? g_feats[(t + 2) * NTAG + n] : 0.f;
        float v[NTAG];
#pragma unroll
        for (int p = 0; p < NTAG; p++)
            v[p] = __shfl_sync(0xffffffffu, fv, p) + tr[p];
        // 5-level tree argmax; tie -> lower index (jnp.argmax first-max rule)
        float bv[16]; int bi[16];
#pragma unroll
        for (int q = 0; q < 16; q++) {
            bool take = v[q + 16] > v[q];
            bv[q] = take ? v[q + 16] : v[q];
            bi[q] = take ? q + 16 : q;
        }
#pragma unroll
        for (int st = 8; st > 0; st >>= 1) {
#pragma unroll
            for (int q = 0; q < 16; q++) {
                if (q < st) {
                    bool take = (bv[q + st] > bv[q]) ||
                                (bv[q + st] == bv[q] && bi[q + st] < bi[q]);
                    bv[q] = take ? bv[q + st] : bv[q];
                    bi[q] = take ? bi[q + st] : bi[q];
                }
            }
        }
        fv = bv[0] + f0;
        bp[t * NTAG + n] = (unsigned char)bi[0];
        f0 = f1; f1 = f2;
    }
    float term = fv + trans[STOP_TAG * NTAG + n];
    float bvv = term;
    int bii = n;
#pragma unroll
    for (int off = 16; off > 0; off >>= 1) {
        float ov = __shfl_down_sync(0xffffffffu, bvv, off);
        int oi = __shfl_down_sync(0xffffffffu, bii, off);
        if (ov > bvv || (ov == bvv && oi < bii)) { bvv = ov; bii = oi; }
    }
    if (n == 0) {
        if (out_size > 0) out[0] = bvv;
        int tag = bii;
        if (out_size > SLEN) out[SLEN] = (float)tag;
        for (int t = SLEN - 2; t >= 0; t--) {
            tag = bp[(t + 1) * NTAG + tag];
            if (1 + t < out_size) out[1 + t] = (float)tag;
        }
    }
}

// ---------------- launch -----------------------------------------------------
extern "C" void kernel_launch(void* const* d_in, const int* in_sizes, int n_in,
                              void* d_out, int out_size)
{
    const int*   sent   = (const int*)d_in[0];
    const float* embed  = (const float*)d_in[1];
    const float* w_ih_f = (const float*)d_in[2];
    const float* w_hh_f = (const float*)d_in[3];
    const float* b_f    = (const float*)d_in[4];
    const float* w_ih_b = (const float*)d_in[5];
    const float* w_hh_b = (const float*)d_in[6];
    const float* b_b    = (const float*)d_in[7];
    const float* w_tag  = (const float*)d_in[8];
    const float* b_tag  = (const float*)d_in[9];
    const float* trans  = (const float*)d_in[10];
    const float* h0     = (const float*)d_in[11];
    const float* c0     = (const float*)d_in[12];
    float* out = (float*)d_out;

    cudaFuncSetAttribute(feats_kernel,
                         cudaFuncAttributeMaxDynamicSharedMemorySize, FEATS_SMEM);
    cudaFuncSetAttribute(viterbi_kernel,
                         cudaFuncAttributeMaxDynamicSharedMemorySize, SLEN * NTAG);

    gather_kernel<<<SLEN, EDIM / 4>>>(sent, embed);

    dim3 gg(SLEN / BM, (4 * HDIM) / BN, 2);
    px_gemm_kernel<<<gg, 256>>>(w_ih_f, b_f, w_ih_b, b_b);

    lstm_kernel<<<16, 256>>>(w_hh_f, w_hh_b, h0, c0);

    feats_kernel<<<SLEN / 32, 256, FEATS_SMEM>>>(w_tag, b_tag);

    viterbi_kernel<<<1, 32, SLEN * NTAG>>>(trans, out, out_size);
}